// round 4
// baseline (speedup 1.0000x reference)
#include <cuda_runtime.h>
#include <cuda_bf16.h>
#include <cstdint>

// Problem constants
// B=32, N=4096, F_IN=F_OUT=64, ALPHA=0.2
// GEMM: G[i, c] = sum_j maskT[i][j] * hflat[j][c],  i in [0,4096), c = b*64+d in [0,2048), j in [0,4096)
//   maskT[i][j] = (j<4095) ? (adj[j+1][i] > 0) : 0     (bf16 exact 0/1)
//   hflat[j][c] = h[b][j][d] split into hi+lo bf16;  h[b][0][:] = 0

// -------- scratch (device globals; no allocation at runtime) --------
__device__ __nv_bfloat16 g_hhi[4096 * 2048];       // 16 MB  [j][c]
__device__ __nv_bfloat16 g_hlo[4096 * 2048];       // 16 MB  [j][c]
__device__ __nv_bfloat16 g_maskT[4096 * 4096];     // 32 MB  [i][j]
__device__ float g_score1[32 * 4096];
__device__ float g_s2[2][32 * 4096];               // two halves (d 0-31 / 32-63), summed in output kernel
__device__ float g_hsumPart[32 * 32 * 64];         // per (b, rowBlk) partial sums
__device__ float g_hsum[32 * 64];

// ============================================================================
// Kernel 1: h = inp @ W  (row 0 zeroed), write bf16 hi/lo split, score1, hsum partials
// grid (32 batches, 32 row-blocks of 128), block 256  (ty = tid/64 in 0..3, d = tid%64)
// ============================================================================
__global__ void k_prep(const float* __restrict__ inp, const float* __restrict__ W,
                       const float* __restrict__ a)
{
    const int b = blockIdx.x;
    const int rowBlk = blockIdx.y;
    const int tid = threadIdx.x;
    const int ty = tid >> 6;
    const int d  = tid & 63;

    __shared__ float sW[64 * 64];
    __shared__ float sIn[4][64];
    __shared__ float sRed[8];
    __shared__ float sHs[4][64];

    for (int t = tid; t < 64 * 64; t += 256) sW[t] = W[t];
    __syncthreads();

    float hs = 0.f;

    for (int r = 0; r < 128; r += 4) {
        const int j = rowBlk * 128 + r + ty;
        sIn[ty][d] = inp[((long)b * 4096 + j) * 64 + d];
        __syncthreads();

        float h = 0.f;
        if (j != 0) {
            #pragma unroll
            for (int f = 0; f < 64; f++) h = fmaf(sIn[ty][f], sW[f * 64 + d], h);
        }

        // bf16 split: h ~= hi + lo
        __nv_bfloat16 hi = __float2bfloat16(h);
        __nv_bfloat16 lo = __float2bfloat16(h - __bfloat162float(hi));
        const int c = b * 64 + d;
        g_hhi[(long)j * 2048 + c] = hi;
        g_hlo[(long)j * 2048 + c] = lo;

        hs += h;

        // score1[b][j] = sum_d h * a1[d][j],  a1[d][j] = a[d*4096 + j]
        float p = h * a[d * 4096 + j];
        #pragma unroll
        for (int o = 16; o; o >>= 1) p += __shfl_down_sync(0xffffffffu, p, o);
        if ((tid & 31) == 0) sRed[tid >> 5] = p;
        __syncthreads();
        if (d == 0) g_score1[b * 4096 + j] = sRed[2 * ty] + sRed[2 * ty + 1];
        __syncthreads();
    }

    sHs[ty][d] = hs;
    __syncthreads();
    if (ty == 0)
        g_hsumPart[(b * 32 + rowBlk) * 64 + d] = sHs[0][d] + sHs[1][d] + sHs[2][d] + sHs[3][d];
}

// ============================================================================
// Kernel 2: maskT transpose:  maskT[i][j] = (j<4095) ? (adj[j+1][i] > 0) : 0
// grid (128 i-tiles, 128 j-tiles), block (32, 8)
// ============================================================================
__global__ void k_mask(const int* __restrict__ adj)
{
    __shared__ float s[32][33];
    const int bi = blockIdx.x * 32;   // i base
    const int bj = blockIdx.y * 32;   // j base
    const int tx = threadIdx.x, ty = threadIdx.y;

    #pragma unroll
    for (int r = ty; r < 32; r += 8) {
        const int j = bj + r;
        const int i = bi + tx;
        int v = (j < 4095) ? adj[(long)(j + 1) * 4096 + i] : 0;
        s[r][tx] = (v > 0) ? 1.f : 0.f;
    }
    __syncthreads();
    #pragma unroll
    for (int r = ty; r < 32; r += 8) {
        const int i = bi + r;
        const int j = bj + tx;
        g_maskT[(long)i * 4096 + j] = __float2bfloat16(s[tx][r]);
    }
}

// ============================================================================
// Kernel 3: finalize hsum (deterministic fixed-order sum of 32 partials)
// ============================================================================
__global__ void k_hsum_final()
{
    const int idx = blockIdx.x * blockDim.x + threadIdx.x;   // 0..2047
    if (idx >= 32 * 64) return;
    const int b = idx >> 6, d = idx & 63;
    float s = 0.f;
    #pragma unroll
    for (int rb = 0; rb < 32; rb++) s += g_hsumPart[(b * 32 + rb) * 64 + d];
    g_hsum[idx] = s;
}

// ============================================================================
// Kernel 4: the GEMM  G = maskT (4096x4096, bf16 0/1) @ hflat (4096x2048, bf16 hi+lo)
// BM=128, BN=128, BK=32, 2-stage cp.async pipeline, mma.sync m16n8k16 bf16,
// epilogue fuses score2[b][i] = sum_d G[i, b*64+d] * a2[d][i]  (no G store, no atomics)
// grid (32, 16), block 256, dyn smem 55296 B
// ============================================================================
#define SM_STAGE 27648
#define SM_A_BYTES 10240            // 128 rows * 80 B (40 bf16, padded from 32)
#define SM_B_BYTES 8704             // 32 rows * 272 B (136 bf16, padded from 128)

__device__ __forceinline__ void cpa16(uint32_t s, const void* g)
{
    asm volatile("cp.async.cg.shared.global [%0], [%1], 16;\n" :: "r"(s), "l"(g) : "memory");
}

__device__ __forceinline__ void load_tile(uint32_t sBase, int stage, int kt,
                                          int im0, int in0, int tid)
{
    const int k0 = kt * 32;
    const uint32_t sA  = sBase + stage * SM_STAGE;
    const uint32_t sBh = sA + SM_A_BYTES;
    const uint32_t sBl = sBh + SM_B_BYTES;

    // A: 128x32 bf16 = 512 16B chunks
    #pragma unroll
    for (int u = 0; u < 2; u++) {
        const int cc = tid + u * 256;
        const int row = cc >> 2, off = cc & 3;
        cpa16(sA + row * 80 + off * 16,
              g_maskT + (long)(im0 + row) * 4096 + k0 + off * 8);
    }
    // Bh/Bl: 32x128 bf16 each = 512 chunks each
    #pragma unroll
    for (int u = 0; u < 2; u++) {
        const int cc = tid + u * 256;
        const int row = cc >> 4, off = cc & 15;
        const long go = (long)(k0 + row) * 2048 + in0 + off * 8;
        cpa16(sBh + row * 272 + off * 16, g_hhi + go);
        cpa16(sBl + row * 272 + off * 16, g_hlo + go);
    }
}

#define MMA_BF16(D, A, Bf)                                                    \
    asm volatile("mma.sync.aligned.m16n8k16.row.col.f32.bf16.bf16.f32 "       \
                 "{%0,%1,%2,%3}, {%4,%5,%6,%7}, {%8,%9}, {%0,%1,%2,%3};\n"    \
                 : "+f"(D[0]), "+f"(D[1]), "+f"(D[2]), "+f"(D[3])             \
                 : "r"(A[0]), "r"(A[1]), "r"(A[2]), "r"(A[3]),                \
                   "r"(Bf[0]), "r"(Bf[1]))

__global__ __launch_bounds__(256, 2) void k_gemm(const float* __restrict__ a)
{
    extern __shared__ char smemRaw[];
    const uint32_t sBase = (uint32_t)__cvta_generic_to_shared(smemRaw);
    const int tid = threadIdx.x;
    const int im0 = blockIdx.x * 128;   // i (M)
    const int in0 = blockIdx.y * 128;   // c (N)
    const int warp = tid >> 5, lane = tid & 31;
    const int wm = warp >> 2;           // 0..1  (64 rows each)
    const int wn = warp & 3;            // 0..3  (32 cols each)

    float acc[4][4][4];
    #pragma unroll
    for (int i = 0; i < 4; i++)
        #pragma unroll
        for (int j = 0; j < 4; j++)
            #pragma unroll
            for (int k = 0; k < 4; k++) acc[i][j][k] = 0.f;

    load_tile(sBase, 0, 0, im0, in0, tid);
    asm volatile("cp.async.commit_group;\n" ::: "memory");

    const int NKT = 4096 / 32;
    for (int kt = 0; kt < NKT; kt++) {
        const int cur = kt & 1;
        if (kt + 1 < NKT) {
            load_tile(sBase, cur ^ 1, kt + 1, im0, in0, tid);
            asm volatile("cp.async.commit_group;\n" ::: "memory");
            asm volatile("cp.async.wait_group 1;\n" ::: "memory");
        } else {
            asm volatile("cp.async.wait_group 0;\n" ::: "memory");
        }
        __syncthreads();

        const uint32_t sA  = sBase + cur * SM_STAGE;
        const uint32_t sBh = sA + SM_A_BYTES;
        const uint32_t sBl = sBh + SM_B_BYTES;

        #pragma unroll
        for (int kk = 0; kk < 32; kk += 16) {
            uint32_t af[4][4];
            #pragma unroll
            for (int mt = 0; mt < 4; mt++) {
                const int row  = wm * 64 + mt * 16 + (lane & 15);
                const int koff = kk + ((lane >> 4) << 3);
                const uint32_t addr = sA + row * 80 + koff * 2;
                asm volatile("ldmatrix.sync.aligned.m8n8.x4.shared.b16 {%0,%1,%2,%3}, [%4];\n"
                             : "=r"(af[mt][0]), "=r"(af[mt][1]),
                               "=r"(af[mt][2]), "=r"(af[mt][3])
                             : "r"(addr));
            }
            uint32_t bh[4][2], bl[4][2];
            #pragma unroll
            for (int nt = 0; nt < 4; nt++) {
                const int r    = kk + (lane & 15);
                const int coln = wn * 32 + nt * 8;
                const uint32_t ah = sBh + r * 272 + coln * 2;
                const uint32_t al = sBl + r * 272 + coln * 2;
                asm volatile("ldmatrix.sync.aligned.m8n8.x2.trans.shared.b16 {%0,%1}, [%2];\n"
                             : "=r"(bh[nt][0]), "=r"(bh[nt][1]) : "r"(ah));
                asm volatile("ldmatrix.sync.aligned.m8n8.x2.trans.shared.b16 {%0,%1}, [%2];\n"
                             : "=r"(bl[nt][0]), "=r"(bl[nt][1]) : "r"(al));
            }
            #pragma unroll
            for (int mt = 0; mt < 4; mt++)
                #pragma unroll
                for (int nt = 0; nt < 4; nt++) {
                    MMA_BF16(acc[mt][nt], af[mt], bh[nt]);
                    MMA_BF16(acc[mt][nt], af[mt], bl[nt]);
                }
        }
        __syncthreads();
    }

    // ---- epilogue: score2 partial = sum_d G[i][c] * a2[d][i] ----
    const int g = lane >> 2, q = lane & 3;
    const int cbase = in0 + wn * 32;       // 32 cols, all inside one batch
    const int bIdx = cbase >> 6;
    #pragma unroll
    for (int mt = 0; mt < 4; mt++) {
        #pragma unroll
        for (int half = 0; half < 2; half++) {
            const int i = im0 + wm * 64 + mt * 16 + g + half * 8;
            float partial = 0.f;
            #pragma unroll
            for (int nt = 0; nt < 4; nt++) {
                const int d0 = (wn * 32 + nt * 8 + 2 * q) & 63;
                const float a2_0 = a[(64 + d0) * 4096 + i];
                const float a2_1 = a[(64 + d0 + 1) * 4096 + i];
                partial = fmaf(acc[mt][nt][half * 2 + 0], a2_0, partial);
                partial = fmaf(acc[mt][nt][half * 2 + 1], a2_1, partial);
            }
            partial += __shfl_xor_sync(0xffffffffu, partial, 1);
            partial += __shfl_xor_sync(0xffffffffu, partial, 2);
            if (q == 0) g_s2[wn & 1][bIdx * 4096 + i] = partial;   // unique writer
        }
    }
}

// ============================================================================
// Kernel 5: output  h_prime[b][i][d] = leaky( score[b][i] * hsum[b][d] )
// one float4 per thread; 8192 blocks x 256 threads
// ============================================================================
__global__ void k_out(float* __restrict__ out)
{
    const int idx = blockIdx.x * 256 + threadIdx.x;   // float4 index
    if (idx >= 32 * 4096 * 16) return;
    const int d4 = idx & 15;
    const int i  = (idx >> 4) & 4095;
    const int b  = idx >> 16;

    float sc = 0.f;
    if (i != 0)
        sc = g_score1[b * 4096 + i] + g_s2[0][b * 4096 + i] + g_s2[1][b * 4096 + i];

    const float4 hs = reinterpret_cast<const float4*>(g_hsum)[b * 16 + d4];
    float4 v;
    float t;
    t = sc * hs.x; v.x = (t >= 0.f) ? t : 0.2f * t;
    t = sc * hs.y; v.y = (t >= 0.f) ? t : 0.2f * t;
    t = sc * hs.z; v.z = (t >= 0.f) ? t : 0.2f * t;
    t = sc * hs.w; v.w = (t >= 0.f) ? t : 0.2f * t;
    reinterpret_cast<float4*>(out)[idx] = v;
}

// ============================================================================
extern "C" void kernel_launch(void* const* d_in, const int* in_sizes, int n_in,
                              void* d_out, int out_size)
{
    // Resolve inputs by element count (robust to ordering):
    // inp: 32*4096*64 = 8388608 f32, W: 64*64 = 4096 f32,
    // a: 128*4096 = 524288 f32, adj: 4096*4096 = 16777216 i32
    const float* inp = nullptr; const float* W = nullptr;
    const float* a = nullptr;   const int* adj = nullptr;
    for (int i = 0; i < n_in; i++) {
        switch (in_sizes[i]) {
            case 8388608:  inp = (const float*)d_in[i]; break;
            case 4096:     W   = (const float*)d_in[i]; break;
            case 524288:   a   = (const float*)d_in[i]; break;
            case 16777216: adj = (const int*)d_in[i];   break;
            default: break;
        }
    }
    if (!inp) inp = (const float*)d_in[0];
    if (!W)   W   = (const float*)d_in[1];
    if (!a)   a   = (const float*)d_in[2];
    if (!adj) adj = (const int*)d_in[3];

    cudaFuncSetAttribute(k_gemm, cudaFuncAttributeMaxDynamicSharedMemorySize, 2 * SM_STAGE);

    k_prep<<<dim3(32, 32), 256>>>(inp, W, a);
    k_mask<<<dim3(128, 128), dim3(32, 8)>>>(adj);
    k_hsum_final<<<8, 256>>>();
    k_gemm<<<dim3(32, 16), 256, 2 * SM_STAGE>>>(a);
    k_out<<<8192, 256>>>((float*)d_out);
}

// round 8
// speedup vs baseline: 1.6654x; 1.6654x over previous
#include <cuda_runtime.h>
#include <cstdint>

#define NN 4096
#define BB 32

// ---------------- scratch (device globals) ----------------
// maskT[i][j] = (j<4095) ? (adj[j+1][i] > 0) : 0          (int8 0/1, 16 MB)
// hhi/hlo: quantized h planes, [c][j], c = b*64+d           (8 MB each)
//   h_int16 = round(h*2048);  hhi = h_int16>>8 (s8), hlo = h_int16&255 (u8)
__device__ __align__(512) char g_maskT[4096u * 4096u];
__device__ __align__(512) char g_hhi[2048u * 4096u];
__device__ __align__(512) unsigned char g_hlo[2048u * 4096u];
__device__ float g_score1[BB * NN];
__device__ float g_score[BB * NN];
__device__ float g_hsumPart[BB * 32 * 64];
__device__ float g_hsum[BB * 64];

__device__ __forceinline__ uint32_t smem_u32(const void* p) {
    uint32_t a;
    asm("{ .reg .u64 t; cvta.to.shared.u64 t, %1; cvt.u32.u64 %0, t; }" : "=r"(a) : "l"(p));
    return a;
}
__device__ __forceinline__ void cpa16(uint32_t s, const void* g) {
    asm volatile("cp.async.cg.shared.global [%0], [%1], 16;\n" :: "r"(s), "l"(g) : "memory");
}

// ============================================================================
// k_prep: h = inp@W (row0 zeroed), int16 quantize -> hi/lo byte planes,
// score1 + hsum partials.  grid(32 b, 32 jb) x 256 thr, dyn smem 69632
// ============================================================================
__global__ void __launch_bounds__(256) k_prep(const float* __restrict__ inp,
                                              const float* __restrict__ W,
                                              const float* __restrict__ a)
{
    extern __shared__ char sm[];
    float* sW  = (float*)sm;                           // [64][64]   16384
    float* sIn = (float*)(sm + 16384);                 // [128][64]  32768
    char*  sHi = sm + 49152;                           // [64][144]   9216
    unsigned char* sLo = (unsigned char*)(sm + 58368); // [64][144]   9216
    float* sS1 = (float*)(sm + 67584);                 // [8][32]     1024
    float* sHs = (float*)(sm + 68608);                 // [4][64]     1024

    const int b = blockIdx.x, jb = blockIdx.y;
    const int tid = threadIdx.x;

    const float4* W4 = (const float4*)W;
    float4* sW4 = (float4*)sW;
    for (int t = tid; t < 1024; t += 256) sW4[t] = W4[t];
    const float4* I4 = (const float4*)(inp + ((long)b * NN + jb * 128) * 64);
    float4* sI4 = (float4*)sIn;
    for (int t = tid; t < 2048; t += 256) sI4[t] = I4[t];
    __syncthreads();

    const int d = tid & 63, grp = tid >> 6;
    float wReg[64];
    #pragma unroll
    for (int f = 0; f < 64; f++) wReg[f] = sW[f * 64 + d];

    float hs = 0.f;
    for (int rr = 0; rr < 32; rr++) {
        const int r = grp * 32 + rr;
        const int j = jb * 128 + r;
        const float* in = sIn + r * 64;
        float h = 0.f;
        #pragma unroll
        for (int f = 0; f < 64; f++) h = fmaf(in[f], wReg[f], h);
        if (j == 0) h = 0.f;

        // quantize to int16, split into bytes
        float hqf = fminf(fmaxf(h * 2048.f, -32768.f), 32767.f);
        int hq = __float2int_rn(hqf);
        sHi[d * 144 + r] = (char)(hq >> 8);            // arithmetic shift
        sLo[d * 144 + r] = (unsigned char)(hq & 255);

        hs += h;
        float p = h * a[d * NN + j];
        #pragma unroll
        for (int o = 16; o; o >>= 1) p += __shfl_down_sync(0xffffffffu, p, o);
        if ((tid & 31) == 0) sS1[(tid >> 5) * 32 + rr] = p;
    }
    sHs[grp * 64 + d] = hs;
    __syncthreads();

    if (tid < 128) {
        const int r = tid, g2 = r >> 5, rr = r & 31;
        g_score1[b * NN + jb * 128 + r] = sS1[(g2 * 2) * 32 + rr] + sS1[(g2 * 2 + 1) * 32 + rr];
    } else if (tid < 192) {
        const int dd = tid - 128;
        g_hsumPart[(b * 32 + jb) * 64 + dd] = sHs[dd] + sHs[64 + dd] + sHs[128 + dd] + sHs[192 + dd];
    }

    // write-out: 1024 16B chunks (hi: 512, lo: 512)
    #pragma unroll
    for (int u = 0; u < 4; u++) {
        const int task = tid + u * 256;
        const int plane = task >> 9;         // 0 = hi, 1 = lo
        const int row = (task >> 3) & 63;    // d index
        const int ch = task & 7;
        uint4 v;
        if (plane == 0) v = *(const uint4*)(sHi + row * 144 + ch * 16);
        else            v = *(const uint4*)((const char*)sLo + row * 144 + ch * 16);
        char* base = plane ? (char*)g_hlo : g_hhi;
        *(uint4*)(base + (b * 64 + row) * NN + jb * 128 + ch * 16) = v;
    }
}

// ============================================================================
// k_mask: maskT[i][j] int8.  block (mI: 128 i's, kt: 64 j's).  grid(32, 64)
// ============================================================================
__global__ void __launch_bounds__(256) k_mask(const int* __restrict__ adj)
{
    __shared__ char sT[128 * 80];
    const int mI = blockIdx.x, kt = blockIdx.y;
    const int tid = threadIdx.x;

    #pragma unroll
    for (int u = 0; u < 8; u++) {
        const int cc = tid + u * 256;        // 0..2047
        const int jl = cc >> 5, ic = (cc & 31) * 4;
        const int j = kt * 64 + jl;
        int4 v;
        if (j < 4095) v = *(const int4*)(adj + (long)(j + 1) * NN + mI * 128 + ic);
        else v = make_int4(0, 0, 0, 0);
        sT[(ic + 0) * 80 + jl] = (char)(v.x > 0);
        sT[(ic + 1) * 80 + jl] = (char)(v.y > 0);
        sT[(ic + 2) * 80 + jl] = (char)(v.z > 0);
        sT[(ic + 3) * 80 + jl] = (char)(v.w > 0);
    }
    __syncthreads();

    #pragma unroll
    for (int u = 0; u < 2; u++) {
        const int task = tid + u * 256;      // 0..511
        const int il = task >> 2, ch = task & 3;
        uint4 v = *(const uint4*)(sT + il * 80 + ch * 16);
        *(uint4*)(g_maskT + (mI * 128 + il) * NN + kt * 64 + ch * 16) = v;
    }
}

// ============================================================================
// k_hsum_final
// ============================================================================
__global__ void k_hsum_final()
{
    const int idx = blockIdx.x * blockDim.x + threadIdx.x;
    if (idx >= BB * 64) return;
    float s = 0.f;
    #pragma unroll
    for (int rb = 0; rb < 32; rb++) s += g_hsumPart[((idx >> 6) * 32 + rb) * 64 + (idx & 63)];
    g_hsum[idx] = s;
}

// ============================================================================
// k_gemm: int8 mma.sync m16n8k32.  BM=128, BN=64, BK=64, 4-stage cp.async.
// A = maskT (s8 0/1), B planes = hhi (s8) / hlo (u8).  Dual s32 accumulators.
// Epilogue fuses score2 = (1/2048) * sum_d (256*Ghi + Glo) * a2[d][i].
// grid (32 mBlk, 32 nBlk=b) x 256 thr, dyn smem 81920
// ============================================================================
#define STG 20480u        // A 128*80 + Bhi 64*80 + Blo 64*80

#define IMMA_S8(D, A, Bf)                                                     \
    asm volatile("mma.sync.aligned.m16n8k32.row.col.s32.s8.s8.s32 "           \
                 "{%0,%1,%2,%3}, {%4,%5,%6,%7}, {%8,%9}, {%0,%1,%2,%3};\n"    \
                 : "+r"((D)[0]), "+r"((D)[1]), "+r"((D)[2]), "+r"((D)[3])     \
                 : "r"((A)[0]), "r"((A)[1]), "r"((A)[2]), "r"((A)[3]),        \
                   "r"((Bf)[0]), "r"((Bf)[1]))
#define IMMA_U8(D, A, Bf)                                                     \
    asm volatile("mma.sync.aligned.m16n8k32.row.col.s32.s8.u8.s32 "           \
                 "{%0,%1,%2,%3}, {%4,%5,%6,%7}, {%8,%9}, {%0,%1,%2,%3};\n"    \
                 : "+r"((D)[0]), "+r"((D)[1]), "+r"((D)[2]), "+r"((D)[3])     \
                 : "r"((A)[0]), "r"((A)[1]), "r"((A)[2]), "r"((A)[3]),        \
                   "r"((Bf)[0]), "r"((Bf)[1]))

__device__ __forceinline__ void gemm_load_stage(uint32_t sBase, int stage, int kt,
                                                int im0, int in0, int tid)
{
    const int k0 = kt * 64;
    const uint32_t sA  = sBase + stage * STG;
    const uint32_t sBh = sA + 10240u;
    const uint32_t sBl = sA + 15360u;
    // A: 128 rows x 64 B = 512 chunks
    #pragma unroll
    for (int u = 0; u < 2; u++) {
        const int c = tid + u * 256;
        const int row = c >> 2, off = c & 3;
        cpa16(sA + row * 80 + off * 16, g_maskT + (im0 + row) * NN + k0 + off * 16);
    }
    // B planes: 64 rows x 64 B each = 256 chunks each
    {
        const int row = tid >> 2, off = tid & 3;
        cpa16(sBh + row * 80 + off * 16, g_hhi + (in0 + row) * NN + k0 + off * 16);
        cpa16(sBl + row * 80 + off * 16, (const char*)g_hlo + (in0 + row) * NN + k0 + off * 16);
    }
}

__global__ void __launch_bounds__(256, 2) k_gemm(const float* __restrict__ a)
{
    extern __shared__ char sm[];
    const uint32_t sBase = smem_u32(sm);
    const int tid = threadIdx.x, warp = tid >> 5, lane = tid & 31;
    const int wm = warp >> 2;            // 0..1 : 64 rows each
    const int wn = warp & 3;             // 0..3 : 16 cols each
    const int im0 = blockIdx.x * 128;    // i base
    const int in0 = blockIdx.y * 64;     // c base (= batch*64)

    int accHi[4][2][4], accLo[4][2][4];
    #pragma unroll
    for (int mt = 0; mt < 4; mt++)
        #pragma unroll
        for (int nt = 0; nt < 2; nt++)
            #pragma unroll
            for (int r = 0; r < 4; r++) { accHi[mt][nt][r] = 0; accLo[mt][nt][r] = 0; }

    // ldmatrix per-lane source selectors
    const int g8 = lane >> 3;
    const int arow = (lane & 7) + 8 * (g8 & 1);
    const int acol = (g8 >> 1) * 16;
    const int brow = lane & 7;
    const int bcol = ((lane >> 3) & 1) * 16;

    // prologue: 3 stages in flight
    #pragma unroll
    for (int s = 0; s < 3; s++) {
        gemm_load_stage(sBase, s, s, im0, in0, tid);
        asm volatile("cp.async.commit_group;\n" ::: "memory");
    }

    #pragma unroll 1
    for (int kt = 0; kt < 64; kt++) {
        asm volatile("cp.async.wait_group 2;\n" ::: "memory");
        __syncthreads();
        if (kt + 3 < 64) gemm_load_stage(sBase, (kt + 3) & 3, kt + 3, im0, in0, tid);
        asm volatile("cp.async.commit_group;\n" ::: "memory");

        const uint32_t sA  = sBase + (kt & 3) * STG;
        const uint32_t sBh = sA + 10240u;
        const uint32_t sBl = sA + 15360u;

        #pragma unroll
        for (int kk = 0; kk < 2; kk++) {
            uint32_t af[4][4];
            #pragma unroll
            for (int mt = 0; mt < 4; mt++) {
                const uint32_t addr = sA + (wm * 64 + mt * 16 + arow) * 80 + kk * 32 + acol;
                asm volatile("ldmatrix.sync.aligned.m8n8.x4.shared.b16 {%0,%1,%2,%3}, [%4];\n"
                             : "=r"(af[mt][0]), "=r"(af[mt][1]),
                               "=r"(af[mt][2]), "=r"(af[mt][3]) : "r"(addr));
            }
            uint32_t bh[2][2], bl[2][2];
            #pragma unroll
            for (int nt = 0; nt < 2; nt++) {
                const uint32_t rowoff = (wn * 16 + nt * 8 + brow) * 80 + kk * 32 + bcol;
                asm volatile("ldmatrix.sync.aligned.m8n8.x2.shared.b16 {%0,%1}, [%2];\n"
                             : "=r"(bh[nt][0]), "=r"(bh[nt][1]) : "r"(sBh + rowoff));
                asm volatile("ldmatrix.sync.aligned.m8n8.x2.shared.b16 {%0,%1}, [%2];\n"
                             : "=r"(bl[nt][0]), "=r"(bl[nt][1]) : "r"(sBl + rowoff));
            }
            #pragma unroll
            for (int mt = 0; mt < 4; mt++)
                #pragma unroll
                for (int nt = 0; nt < 2; nt++) {
                    IMMA_S8(accHi[mt][nt], af[mt], bh[nt]);
                    IMMA_U8(accLo[mt][nt], af[mt], bl[nt]);
                }
        }
    }

    // ---- epilogue: score2 = (1/2048) * sum_d (256*Ghi + Glo) * a2[d][i] ----
    __syncthreads();
    float* sRed = (float*)sm;            // [128][4]
    const int qid = lane >> 2, mem = lane & 3;
    #pragma unroll
    for (int mt = 0; mt < 4; mt++) {
        #pragma unroll
        for (int sub = 0; sub < 2; sub++) {
            const int i = im0 + wm * 64 + mt * 16 + qid + 8 * sub;
            float part = 0.f;
            #pragma unroll
            for (int nt = 0; nt < 2; nt++) {
                #pragma unroll
                for (int cp = 0; cp < 2; cp++) {
                    const int full = (accHi[mt][nt][sub * 2 + cp] << 8) + accLo[mt][nt][sub * 2 + cp];
                    const int dd = wn * 16 + nt * 8 + 2 * mem + cp;
                    part = fmaf((float)full, __ldg(&a[(64 + dd) * NN + i]), part);
                }
            }
            part += __shfl_xor_sync(0xffffffffu, part, 1);
            part += __shfl_xor_sync(0xffffffffu, part, 2);
            if (mem == 0) sRed[(wm * 64 + mt * 16 + qid + 8 * sub) * 4 + wn] = part;
        }
    }
    __syncthreads();
    if (tid < 128) {
        const int i = im0 + tid;
        const float s2 = (sRed[tid * 4 + 0] + sRed[tid * 4 + 1] +
                          sRed[tid * 4 + 2] + sRed[tid * 4 + 3]) * (1.f / 2048.f);
        g_score[blockIdx.y * NN + i] = s2 + g_score1[blockIdx.y * NN + i];
    }
}

// ============================================================================
// k_out: h_prime = leaky( score[b][i] * hsum[b][d] )
// ============================================================================
__global__ void __launch_bounds__(256) k_out(float* __restrict__ out)
{
    const int idx = blockIdx.x * 256 + threadIdx.x;   // float4 index, exactly 2M
    const int d4 = idx & 15;
    const int i  = (idx >> 4) & 4095;
    const int b  = idx >> 16;
    const float sc = (i == 0) ? 0.f : g_score[b * NN + i];
    const float4 hs = reinterpret_cast<const float4*>(g_hsum)[b * 16 + d4];
    float4 v; float t;
    t = sc * hs.x; v.x = (t >= 0.f) ? t : 0.2f * t;
    t = sc * hs.y; v.y = (t >= 0.f) ? t : 0.2f * t;
    t = sc * hs.z; v.z = (t >= 0.f) ? t : 0.2f * t;
    t = sc * hs.w; v.w = (t >= 0.f) ? t : 0.2f * t;
    reinterpret_cast<float4*>(out)[idx] = v;
}

// ============================================================================
extern "C" void kernel_launch(void* const* d_in, const int* in_sizes, int n_in,
                              void* d_out, int out_size)
{
    const float* inp = nullptr; const float* W = nullptr;
    const float* a = nullptr;   const int* adj = nullptr;
    for (int i = 0; i < n_in; i++) {
        switch (in_sizes[i]) {
            case 8388608:  inp = (const float*)d_in[i]; break;
            case 4096:     W   = (const float*)d_in[i]; break;
            case 524288:   a   = (const float*)d_in[i]; break;
            case 16777216: adj = (const int*)d_in[i];   break;
            default: break;
        }
    }
    if (!inp) inp = (const float*)d_in[0];
    if (!W)   W   = (const float*)d_in[1];
    if (!a)   a   = (const float*)d_in[2];
    if (!adj) adj = (const int*)d_in[3];

    cudaFuncSetAttribute(k_prep, cudaFuncAttributeMaxDynamicSharedMemorySize, 69632);
    cudaFuncSetAttribute(k_gemm, cudaFuncAttributeMaxDynamicSharedMemorySize, 4 * STG);

    k_prep<<<dim3(32, 32), 256, 69632>>>(inp, W, a);
    k_mask<<<dim3(32, 64), 256>>>(adj);
    k_hsum_final<<<8, 256>>>();
    k_gemm<<<dim3(32, 32), 256, 4 * STG>>>(a);
    k_out<<<8192, 256>>>((float*)d_out);
}

// round 11
// speedup vs baseline: 1.9840x; 1.1913x over previous
#include <cuda_runtime.h>
#include <cstdint>

#define NN 4096
#define BB 32

// ---------------- scratch (device globals) ----------------
// maskT[i][j] = (j<4095) ? (adj[j+1][i] > 0) : 0          (int8 0/1, 16 MB)
// hhi/hlo: quantized h planes, [c][j], c = b*64+d           (8 MB each)
//   h_int16 = round(h*2048);  hhi = h_int16>>8 (s8), hlo = h_int16&255 (u8)
__device__ __align__(512) char g_maskT[4096u * 4096u];
__device__ __align__(512) char g_hhi[2048u * 4096u];
__device__ __align__(512) unsigned char g_hlo[2048u * 4096u];
__device__ float g_score1[BB * NN];
__device__ float g_score[BB * NN];
__device__ float g_hsumPart[BB * 32 * 64];
__device__ float g_hsum[BB * 64];

__device__ __forceinline__ uint32_t smem_u32(const void* p) {
    uint32_t a;
    asm("{ .reg .u64 t; cvta.to.shared.u64 t, %1; cvt.u32.u64 %0, t; }" : "=r"(a) : "l"(p));
    return a;
}
__device__ __forceinline__ void cpa16(uint32_t s, const void* g) {
    asm volatile("cp.async.cg.shared.global [%0], [%1], 16;\n" :: "r"(s), "l"(g) : "memory");
}

// ============================================================================
// k_prep: h = inp@W (row0 zeroed), int16 quantize -> hi/lo byte planes,
// score1 (a1 staged in smem, coalesced) + hsum partials.
// grid(32 b, 32 jb) x 256 thr, dyn smem 102656
// ============================================================================
__global__ void __launch_bounds__(256) k_prep(const float* __restrict__ inp,
                                              const float* __restrict__ W,
                                              const float* __restrict__ a)
{
    extern __shared__ char sm[];
    float* sW  = (float*)sm;                            // [64][64]    16384
    float* sIn = (float*)(sm + 16384);                  // [128][64]   32768
    float* sA1 = (float*)(sm + 49152);                  // [64][129]   33024
    char*  sHi = sm + 82176;                            // [64][144]    9216
    unsigned char* sLo = (unsigned char*)(sm + 91392);  // [64][144]    9216
    float* sS1 = (float*)(sm + 100608);                 // [8][32]      1024
    float* sHs = (float*)(sm + 101632);                 // [4][64]      1024

    const int b = blockIdx.x, jb = blockIdx.y;
    const int tid = threadIdx.x;

    const float4* W4 = (const float4*)W;
    float4* sW4 = (float4*)sW;
    for (int t = tid; t < 1024; t += 256) sW4[t] = W4[t];
    const float4* I4 = (const float4*)(inp + ((long)b * NN + jb * 128) * 64);
    float4* sI4 = (float4*)sIn;
    for (int t = tid; t < 2048; t += 256) sI4[t] = I4[t];
    // stage a1 tile: rows d=0..63, cols j = jb*128 .. +128, coalesced
    for (int t = tid; t < 2048; t += 256) {
        const int dd = t >> 5, c4 = t & 31;
        const float4 v = *(const float4*)(a + (long)dd * NN + jb * 128 + c4 * 4);
        float* dst = sA1 + dd * 129 + c4 * 4;
        dst[0] = v.x; dst[1] = v.y; dst[2] = v.z; dst[3] = v.w;
    }
    __syncthreads();

    const int d = tid & 63, grp = tid >> 6;
    float wReg[64];
    #pragma unroll
    for (int f = 0; f < 64; f++) wReg[f] = sW[f * 64 + d];

    float hs = 0.f;
    for (int rr = 0; rr < 32; rr++) {
        const int r = grp * 32 + rr;
        const int j = jb * 128 + r;
        const float* in = sIn + r * 64;
        float h = 0.f;
        #pragma unroll
        for (int f = 0; f < 64; f++) h = fmaf(in[f], wReg[f], h);
        if (j == 0) h = 0.f;

        // quantize to int16, split into bytes
        float hqf = fminf(fmaxf(h * 2048.f, -32768.f), 32767.f);
        int hq = __float2int_rn(hqf);
        sHi[d * 144 + r] = (char)(hq >> 8);
        sLo[d * 144 + r] = (unsigned char)(hq & 255);

        hs += h;
        float p = h * sA1[d * 129 + r];
        #pragma unroll
        for (int o = 16; o; o >>= 1) p += __shfl_down_sync(0xffffffffu, p, o);
        if ((tid & 31) == 0) sS1[(tid >> 5) * 32 + rr] = p;
    }
    sHs[grp * 64 + d] = hs;
    __syncthreads();

    if (tid < 128) {
        const int r = tid, g2 = r >> 5, rr = r & 31;
        g_score1[b * NN + jb * 128 + r] = sS1[(g2 * 2) * 32 + rr] + sS1[(g2 * 2 + 1) * 32 + rr];
    } else if (tid < 192) {
        const int dd = tid - 128;
        g_hsumPart[(b * 32 + jb) * 64 + dd] = sHs[dd] + sHs[64 + dd] + sHs[128 + dd] + sHs[192 + dd];
    }

    // write-out: 1024 16B chunks (hi: 512, lo: 512)
    #pragma unroll
    for (int u = 0; u < 4; u++) {
        const int task = tid + u * 256;
        const int plane = task >> 9;
        const int row = (task >> 3) & 63;
        const int ch = task & 7;
        uint4 v;
        if (plane == 0) v = *(const uint4*)(sHi + row * 144 + ch * 16);
        else            v = *(const uint4*)((const char*)sLo + row * 144 + ch * 16);
        char* base = plane ? (char*)g_hlo : g_hhi;
        *(uint4*)(base + (b * 64 + row) * NN + jb * 128 + ch * 16) = v;
    }
}

// ============================================================================
// k_mask: maskT[i][j] int8.  block (mI: 128 i's, kt: 64 j's).  grid(32, 64)
// ============================================================================
__global__ void __launch_bounds__(256) k_mask(const int* __restrict__ adj)
{
    __shared__ char sT[128 * 80];
    const int mI = blockIdx.x, kt = blockIdx.y;
    const int tid = threadIdx.x;

    #pragma unroll
    for (int u = 0; u < 8; u++) {
        const int cc = tid + u * 256;
        const int jl = cc >> 5, ic = (cc & 31) * 4;
        const int j = kt * 64 + jl;
        int4 v;
        if (j < 4095) v = *(const int4*)(adj + (long)(j + 1) * NN + mI * 128 + ic);
        else v = make_int4(0, 0, 0, 0);
        sT[(ic + 0) * 80 + jl] = (char)(v.x > 0);
        sT[(ic + 1) * 80 + jl] = (char)(v.y > 0);
        sT[(ic + 2) * 80 + jl] = (char)(v.z > 0);
        sT[(ic + 3) * 80 + jl] = (char)(v.w > 0);
    }
    __syncthreads();

    #pragma unroll
    for (int u = 0; u < 2; u++) {
        const int task = tid + u * 256;
        const int il = task >> 2, ch = task & 3;
        uint4 v = *(const uint4*)(sT + il * 80 + ch * 16);
        *(uint4*)(g_maskT + (mI * 128 + il) * NN + kt * 64 + ch * 16) = v;
    }
}

// ============================================================================
// k_hsum_final
// ============================================================================
__global__ void k_hsum_final()
{
    const int idx = blockIdx.x * blockDim.x + threadIdx.x;
    if (idx >= BB * 64) return;
    float s = 0.f;
    #pragma unroll
    for (int rb = 0; rb < 32; rb++) s += g_hsumPart[((idx >> 6) * 32 + rb) * 64 + (idx & 63)];
    g_hsum[idx] = s;
}

// ============================================================================
// k_gemm: int8 mma.sync m16n8k32.  BM=128, BN=64, BK=128, 3-stage cp.async.
// A = maskT (s8 0/1), B planes = hhi (s8) / hlo (u8), fused hi/lo ldsm.x4.
// Epilogue fuses score2 = (1/2048) * sum_d (256*Ghi + Glo) * a2[d][i].
// grid (32 mBlk, 32 nBlk=b) x 256 thr, dyn smem 110592
// ============================================================================
#define STG 36864u        // A 128*144 (18432) + Bhi 64*144 (9216) + Blo 64*144 (9216)
#define B_HI_OFF 18432u
#define B_LO_OFF 27648u
#define NKT 32

#define IMMA_S8(D, A, B0, B1)                                                 \
    asm volatile("mma.sync.aligned.m16n8k32.row.col.s32.s8.s8.s32 "           \
                 "{%0,%1,%2,%3}, {%4,%5,%6,%7}, {%8,%9}, {%0,%1,%2,%3};\n"    \
                 : "+r"((D)[0]), "+r"((D)[1]), "+r"((D)[2]), "+r"((D)[3])     \
                 : "r"((A)[0]), "r"((A)[1]), "r"((A)[2]), "r"((A)[3]),        \
                   "r"(B0), "r"(B1))
#define IMMA_U8(D, A, B0, B1)                                                 \
    asm volatile("mma.sync.aligned.m16n8k32.row.col.s32.s8.u8.s32 "           \
                 "{%0,%1,%2,%3}, {%4,%5,%6,%7}, {%8,%9}, {%0,%1,%2,%3};\n"    \
                 : "+r"((D)[0]), "+r"((D)[1]), "+r"((D)[2]), "+r"((D)[3])     \
                 : "r"((A)[0]), "r"((A)[1]), "r"((A)[2]), "r"((A)[3]),        \
                   "r"(B0), "r"(B1))

__device__ __forceinline__ void gemm_load_stage(uint32_t sBase, int stage, int kt,
                                                int im0, int in0, int tid)
{
    const int k0 = kt * 128;
    const uint32_t sA = sBase + stage * STG;
    // A: 128 rows x 128 B = 1024 chunks
    #pragma unroll
    for (int u = 0; u < 4; u++) {
        const int c = tid + u * 256;
        const int row = c >> 3, off = c & 7;
        cpa16(sA + row * 144 + off * 16, g_maskT + (im0 + row) * NN + k0 + off * 16);
    }
    // B planes: 64 rows x 128 B each = 512 chunks each
    #pragma unroll
    for (int u = 0; u < 2; u++) {
        const int c = tid + u * 256;
        const int row = c >> 3, off = c & 7;
        cpa16(sA + B_HI_OFF + row * 144 + off * 16, g_hhi + (in0 + row) * NN + k0 + off * 16);
        cpa16(sA + B_LO_OFF + row * 144 + off * 16, (const char*)g_hlo + (in0 + row) * NN + k0 + off * 16);
    }
}

__global__ void __launch_bounds__(256, 2) k_gemm(const float* __restrict__ a)
{
    extern __shared__ char sm[];
    const uint32_t sBase = smem_u32(sm);
    const int tid = threadIdx.x, warp = tid >> 5, lane = tid & 31;
    const int wm = warp >> 2;            // 0..1 : 64 rows each
    const int wn = warp & 3;             // 0..3 : 16 cols each
    const int im0 = blockIdx.x * 128;    // i base
    const int in0 = blockIdx.y * 64;     // c base (= batch*64)

    int accHi[4][2][4], accLo[4][2][4];
    #pragma unroll
    for (int mt = 0; mt < 4; mt++)
        #pragma unroll
        for (int nt = 0; nt < 2; nt++)
            #pragma unroll
            for (int r = 0; r < 4; r++) { accHi[mt][nt][r] = 0; accLo[mt][nt][r] = 0; }

    // ldmatrix per-lane source offsets
    const int g8 = lane >> 3;
    const int arow = (lane & 7) + 8 * (g8 & 1);
    const int acol = (g8 >> 1) * 16;
    // fused B x4: groups g0,g1 -> hi plane (k lo/hi 16B), g2,g3 -> lo plane
    const uint32_t bOff = ((uint32_t)(wn * 16 + (lane & 7)) * 144u) +
                          (uint32_t)((g8 & 1) * 16) +
                          (uint32_t)((g8 >> 1) * (B_LO_OFF - B_HI_OFF));

    // prologue: 2 stages in flight
    #pragma unroll
    for (int s = 0; s < 2; s++) {
        gemm_load_stage(sBase, s, s, im0, in0, tid);
        asm volatile("cp.async.commit_group;\n" ::: "memory");
    }

    #pragma unroll 1
    for (int kt = 0; kt < NKT; kt++) {
        asm volatile("cp.async.wait_group 1;\n" ::: "memory");
        __syncthreads();
        if (kt + 2 < NKT) gemm_load_stage(sBase, (kt + 2) % 3, kt + 2, im0, in0, tid);
        asm volatile("cp.async.commit_group;\n" ::: "memory");

        const uint32_t sA  = sBase + (kt % 3) * STG;
        const uint32_t sBh = sA + B_HI_OFF;

        #pragma unroll
        for (int kk = 0; kk < 4; kk++) {
            uint32_t af[4][4];
            #pragma unroll
            for (int mt = 0; mt < 4; mt++) {
                const uint32_t addr = sA + (wm * 64 + mt * 16 + arow) * 144 + kk * 32 + acol;
                asm volatile("ldmatrix.sync.aligned.m8n8.x4.shared.b16 {%0,%1,%2,%3}, [%4];\n"
                             : "=r"(af[mt][0]), "=r"(af[mt][1]),
                               "=r"(af[mt][2]), "=r"(af[mt][3]) : "r"(addr));
            }
            uint32_t bf[2][4];
            #pragma unroll
            for (int nt = 0; nt < 2; nt++) {
                const uint32_t addr = sBh + bOff + nt * 8 * 144 + kk * 32;
                asm volatile("ldmatrix.sync.aligned.m8n8.x4.shared.b16 {%0,%1,%2,%3}, [%4];\n"
                             : "=r"(bf[nt][0]), "=r"(bf[nt][1]),
                               "=r"(bf[nt][2]), "=r"(bf[nt][3]) : "r"(addr));
            }
            #pragma unroll
            for (int mt = 0; mt < 4; mt++)
                #pragma unroll
                for (int nt = 0; nt < 2; nt++) {
                    IMMA_S8(accHi[mt][nt], af[mt], bf[nt][0], bf[nt][1]);
                    IMMA_U8(accLo[mt][nt], af[mt], bf[nt][2], bf[nt][3]);
                }
        }
    }

    // ---- epilogue: score2 = (1/2048) * sum_d (256*Ghi + Glo) * a2[d][i] ----
    __syncthreads();
    float* sRed = (float*)sm;            // [128][4]
    const int qid = lane >> 2, mem = lane & 3;
    #pragma unroll
    for (int mt = 0; mt < 4; mt++) {
        #pragma unroll
        for (int sub = 0; sub < 2; sub++) {
            const int i = im0 + wm * 64 + mt * 16 + qid + 8 * sub;
            float part = 0.f;
            #pragma unroll
            for (int nt = 0; nt < 2; nt++) {
                #pragma unroll
                for (int cp = 0; cp < 2; cp++) {
                    const int full = (accHi[mt][nt][sub * 2 + cp] << 8) + accLo[mt][nt][sub * 2 + cp];
                    const int dd = wn * 16 + nt * 8 + 2 * mem + cp;
                    part = fmaf((float)full, __ldg(&a[(64 + dd) * NN + i]), part);
                }
            }
            part += __shfl_xor_sync(0xffffffffu, part, 1);
            part += __shfl_xor_sync(0xffffffffu, part, 2);
            if (mem == 0) sRed[(wm * 64 + mt * 16 + qid + 8 * sub) * 4 + wn] = part;
        }
    }
    __syncthreads();
    if (tid < 128) {
        const int i = im0 + tid;
        const float s2 = (sRed[tid * 4 + 0] + sRed[tid * 4 + 1] +
                          sRed[tid * 4 + 2] + sRed[tid * 4 + 3]) * (1.f / 2048.f);
        g_score[blockIdx.y * NN + i] = s2 + g_score1[blockIdx.y * NN + i];
    }
}

// ============================================================================
// k_out: h_prime = leaky( score[b][i] * hsum[b][d] )
// ============================================================================
__global__ void __launch_bounds__(256) k_out(float* __restrict__ out)
{
    const int idx = blockIdx.x * 256 + threadIdx.x;
    const int d4 = idx & 15;
    const int i  = (idx >> 4) & 4095;
    const int b  = idx >> 16;
    const float sc = (i == 0) ? 0.f : g_score[b * NN + i];
    const float4 hs = reinterpret_cast<const float4*>(g_hsum)[b * 16 + d4];
    float4 v; float t;
    t = sc * hs.x; v.x = (t >= 0.f) ? t : 0.2f * t;
    t = sc * hs.y; v.y = (t >= 0.f) ? t : 0.2f * t;
    t = sc * hs.z; v.z = (t >= 0.f) ? t : 0.2f * t;
    t = sc * hs.w; v.w = (t >= 0.f) ? t : 0.2f * t;
    reinterpret_cast<float4*>(out)[idx] = v;
}

// ============================================================================
extern "C" void kernel_launch(void* const* d_in, const int* in_sizes, int n_in,
                              void* d_out, int out_size)
{
    const float* inp = nullptr; const float* W = nullptr;
    const float* a = nullptr;   const int* adj = nullptr;
    for (int i = 0; i < n_in; i++) {
        switch (in_sizes[i]) {
            case 8388608:  inp = (const float*)d_in[i]; break;
            case 4096:     W   = (const float*)d_in[i]; break;
            case 524288:   a   = (const float*)d_in[i]; break;
            case 16777216: adj = (const int*)d_in[i];   break;
            default: break;
        }
    }
    if (!inp) inp = (const float*)d_in[0];
    if (!W)   W   = (const float*)d_in[1];
    if (!a)   a   = (const float*)d_in[2];
    if (!adj) adj = (const int*)d_in[3];

    cudaFuncSetAttribute(k_prep, cudaFuncAttributeMaxDynamicSharedMemorySize, 102656);
    cudaFuncSetAttribute(k_gemm, cudaFuncAttributeMaxDynamicSharedMemorySize, 3 * STG);

    k_prep<<<dim3(32, 32), 256, 102656>>>(inp, W, a);
    k_mask<<<dim3(32, 64), 256>>>(adj);
    k_hsum_final<<<8, 256>>>();
    k_gemm<<<dim3(32, 32), 256, 3 * STG>>>(a);
    k_out<<<8192, 256>>>((float*)d_out);
}

// round 12
// speedup vs baseline: 1.9939x; 1.0050x over previous
#include <cuda_runtime.h>
#include <cstdint>

#define NN 4096
#define BB 32

// ---------------- scratch (device globals) ----------------
// maskT[i][j] = (j<4095) ? (adj[j+1][i] > 0) : 0          (int8 0/1, 16 MB)
// hhi/hlo: quantized h planes, [c][j], c = b*64+d           (8 MB each)
//   h_int16 = round(h*2048);  hhi = h_int16>>8 (s8), hlo = h_int16&255 (u8)
__device__ __align__(512) char g_maskT[4096u * 4096u];
__device__ __align__(512) char g_hhi[2048u * 4096u];
__device__ __align__(512) unsigned char g_hlo[2048u * 4096u];
__device__ float g_score1[BB * NN];
__device__ float g_score[BB * NN];
__device__ float g_hsumPart[BB * 32 * 64];
__device__ float g_hsum[BB * 64];

__device__ __forceinline__ uint32_t smem_u32(const void* p) {
    uint32_t a;
    asm("{ .reg .u64 t; cvta.to.shared.u64 t, %1; cvt.u32.u64 %0, t; }" : "=r"(a) : "l"(p));
    return a;
}
__device__ __forceinline__ void cpa16(uint32_t s, const void* g) {
    asm volatile("cp.async.cg.shared.global [%0], [%1], 16;\n" :: "r"(s), "l"(g) : "memory");
}

// ============================================================================
// k_prep: h = inp@W (row0 zeroed), int16 quantize -> hi/lo byte planes,
// score1 (a1 staged in smem, coalesced) + hsum partials.
// grid(32 b, 32 jb) x 256 thr, dyn smem 102656
// ============================================================================
__global__ void __launch_bounds__(256) k_prep(const float* __restrict__ inp,
                                              const float* __restrict__ W,
                                              const float* __restrict__ a)
{
    extern __shared__ char sm[];
    float* sW  = (float*)sm;                            // [64][64]    16384
    float* sIn = (float*)(sm + 16384);                  // [128][64]   32768
    float* sA1 = (float*)(sm + 49152);                  // [64][129]   33024
    char*  sHi = sm + 82176;                            // [64][144]    9216
    unsigned char* sLo = (unsigned char*)(sm + 91392);  // [64][144]    9216
    float* sS1 = (float*)(sm + 100608);                 // [8][32]      1024
    float* sHs = (float*)(sm + 101632);                 // [4][64]      1024

    const int b = blockIdx.x, jb = blockIdx.y;
    const int tid = threadIdx.x;

    const float4* W4 = (const float4*)W;
    float4* sW4 = (float4*)sW;
    for (int t = tid; t < 1024; t += 256) sW4[t] = W4[t];
    const float4* I4 = (const float4*)(inp + ((long)b * NN + jb * 128) * 64);
    float4* sI4 = (float4*)sIn;
    for (int t = tid; t < 2048; t += 256) sI4[t] = I4[t];
    // stage a1 tile: rows d=0..63, cols j = jb*128 .. +128, coalesced
    for (int t = tid; t < 2048; t += 256) {
        const int dd = t >> 5, c4 = t & 31;
        const float4 v = *(const float4*)(a + (long)dd * NN + jb * 128 + c4 * 4);
        float* dst = sA1 + dd * 129 + c4 * 4;
        dst[0] = v.x; dst[1] = v.y; dst[2] = v.z; dst[3] = v.w;
    }
    __syncthreads();

    const int d = tid & 63, grp = tid >> 6;
    float wReg[64];
    #pragma unroll
    for (int f = 0; f < 64; f++) wReg[f] = sW[f * 64 + d];

    float hs = 0.f;
    for (int rr = 0; rr < 32; rr++) {
        const int r = grp * 32 + rr;
        const int j = jb * 128 + r;
        const float* in = sIn + r * 64;
        float h = 0.f;
        #pragma unroll
        for (int f = 0; f < 64; f++) h = fmaf(in[f], wReg[f], h);
        if (j == 0) h = 0.f;

        // quantize to int16, split into bytes
        float hqf = fminf(fmaxf(h * 2048.f, -32768.f), 32767.f);
        int hq = __float2int_rn(hqf);
        sHi[d * 144 + r] = (char)(hq >> 8);
        sLo[d * 144 + r] = (unsigned char)(hq & 255);

        hs += h;
        float p = h * sA1[d * 129 + r];
        #pragma unroll
        for (int o = 16; o; o >>= 1) p += __shfl_down_sync(0xffffffffu, p, o);
        if ((tid & 31) == 0) sS1[(tid >> 5) * 32 + rr] = p;
    }
    sHs[grp * 64 + d] = hs;
    __syncthreads();

    if (tid < 128) {
        const int r = tid, g2 = r >> 5, rr = r & 31;
        g_score1[b * NN + jb * 128 + r] = sS1[(g2 * 2) * 32 + rr] + sS1[(g2 * 2 + 1) * 32 + rr];
    } else if (tid < 192) {
        const int dd = tid - 128;
        g_hsumPart[(b * 32 + jb) * 64 + dd] = sHs[dd] + sHs[64 + dd] + sHs[128 + dd] + sHs[192 + dd];
    }

    // write-out: 1024 16B chunks (hi: 512, lo: 512)
    #pragma unroll
    for (int u = 0; u < 4; u++) {
        const int task = tid + u * 256;
        const int plane = task >> 9;
        const int row = (task >> 3) & 63;
        const int ch = task & 7;
        uint4 v;
        if (plane == 0) v = *(const uint4*)(sHi + row * 144 + ch * 16);
        else            v = *(const uint4*)((const char*)sLo + row * 144 + ch * 16);
        char* base = plane ? (char*)g_hlo : g_hhi;
        *(uint4*)(base + (b * 64 + row) * NN + jb * 128 + ch * 16) = v;
    }
}

// ============================================================================
// k_mask: maskT[i][j] int8.  block (mI: 128 i's, kt: 64 j's).  grid(32, 64)
// ============================================================================
__global__ void __launch_bounds__(256) k_mask(const int* __restrict__ adj)
{
    __shared__ char sT[128 * 80];
    const int mI = blockIdx.x, kt = blockIdx.y;
    const int tid = threadIdx.x;

    #pragma unroll
    for (int u = 0; u < 8; u++) {
        const int cc = tid + u * 256;
        const int jl = cc >> 5, ic = (cc & 31) * 4;
        const int j = kt * 64 + jl;
        int4 v;
        if (j < 4095) v = *(const int4*)(adj + (long)(j + 1) * NN + mI * 128 + ic);
        else v = make_int4(0, 0, 0, 0);
        sT[(ic + 0) * 80 + jl] = (char)(v.x > 0);
        sT[(ic + 1) * 80 + jl] = (char)(v.y > 0);
        sT[(ic + 2) * 80 + jl] = (char)(v.z > 0);
        sT[(ic + 3) * 80 + jl] = (char)(v.w > 0);
    }
    __syncthreads();

    #pragma unroll
    for (int u = 0; u < 2; u++) {
        const int task = tid + u * 256;
        const int il = task >> 2, ch = task & 3;
        uint4 v = *(const uint4*)(sT + il * 80 + ch * 16);
        *(uint4*)(g_maskT + (mI * 128 + il) * NN + kt * 64 + ch * 16) = v;
    }
}

// ============================================================================
// k_hsum_final
// ============================================================================
__global__ void k_hsum_final()
{
    const int idx = blockIdx.x * blockDim.x + threadIdx.x;
    if (idx >= BB * 64) return;
    float s = 0.f;
    #pragma unroll
    for (int rb = 0; rb < 32; rb++) s += g_hsumPart[((idx >> 6) * 32 + rb) * 64 + (idx & 63)];
    g_hsum[idx] = s;
}

// ============================================================================
// k_gemm: int8 mma.sync m16n8k32.  BM=128, BN=64, BK=128, 3-stage cp.async.
// A = maskT (s8 0/1), B planes = hhi (s8) / hlo (u8), fused hi/lo ldsm.x4.
// Epilogue fuses score2 = (1/2048) * sum_d (256*Ghi + Glo) * a2[d][i].
// grid (32 mBlk, 32 nBlk=b) x 256 thr, dyn smem 110592
// ============================================================================
#define STG 36864u        // A 128*144 (18432) + Bhi 64*144 (9216) + Blo 64*144 (9216)
#define B_HI_OFF 18432u
#define B_LO_OFF 27648u
#define NKT 32

#define IMMA_S8(D, A, B0, B1)                                                 \
    asm volatile("mma.sync.aligned.m16n8k32.row.col.s32.s8.s8.s32 "           \
                 "{%0,%1,%2,%3}, {%4,%5,%6,%7}, {%8,%9}, {%0,%1,%2,%3};\n"    \
                 : "+r"((D)[0]), "+r"((D)[1]), "+r"((D)[2]), "+r"((D)[3])     \
                 : "r"((A)[0]), "r"((A)[1]), "r"((A)[2]), "r"((A)[3]),        \
                   "r"(B0), "r"(B1))
#define IMMA_U8(D, A, B0, B1)                                                 \
    asm volatile("mma.sync.aligned.m16n8k32.row.col.s32.s8.u8.s32 "           \
                 "{%0,%1,%2,%3}, {%4,%5,%6,%7}, {%8,%9}, {%0,%1,%2,%3};\n"    \
                 : "+r"((D)[0]), "+r"((D)[1]), "+r"((D)[2]), "+r"((D)[3])     \
                 : "r"((A)[0]), "r"((A)[1]), "r"((A)[2]), "r"((A)[3]),        \
                   "r"(B0), "r"(B1))

__device__ __forceinline__ void gemm_load_stage(uint32_t sBase, int stage, int kt,
                                                int im0, int in0, int tid)
{
    const int k0 = kt * 128;
    const uint32_t sA = sBase + stage * STG;
    // A: 128 rows x 128 B = 1024 chunks
    #pragma unroll
    for (int u = 0; u < 4; u++) {
        const int c = tid + u * 256;
        const int row = c >> 3, off = c & 7;
        cpa16(sA + row * 144 + off * 16, g_maskT + (im0 + row) * NN + k0 + off * 16);
    }
    // B planes: 64 rows x 128 B each = 512 chunks each
    #pragma unroll
    for (int u = 0; u < 2; u++) {
        const int c = tid + u * 256;
        const int row = c >> 3, off = c & 7;
        cpa16(sA + B_HI_OFF + row * 144 + off * 16, g_hhi + (in0 + row) * NN + k0 + off * 16);
        cpa16(sA + B_LO_OFF + row * 144 + off * 16, (const char*)g_hlo + (in0 + row) * NN + k0 + off * 16);
    }
}

__global__ void __launch_bounds__(256, 2) k_gemm(const float* __restrict__ a)
{
    extern __shared__ char sm[];
    const uint32_t sBase = smem_u32(sm);
    const int tid = threadIdx.x, warp = tid >> 5, lane = tid & 31;
    const int wm = warp >> 2;            // 0..1 : 64 rows each
    const int wn = warp & 3;             // 0..3 : 16 cols each
    const int im0 = blockIdx.x * 128;    // i base
    const int in0 = blockIdx.y * 64;     // c base (= batch*64)

    int accHi[4][2][4], accLo[4][2][4];
    #pragma unroll
    for (int mt = 0; mt < 4; mt++)
        #pragma unroll
        for (int nt = 0; nt < 2; nt++)
            #pragma unroll
            for (int r = 0; r < 4; r++) { accHi[mt][nt][r] = 0; accLo[mt][nt][r] = 0; }

    // ldmatrix per-lane source offsets
    const int g8 = lane >> 3;
    const int arow = (lane & 7) + 8 * (g8 & 1);
    const int acol = (g8 >> 1) * 16;
    // fused B x4: groups g0,g1 -> hi plane (k lo/hi 16B), g2,g3 -> lo plane
    const uint32_t bOff = ((uint32_t)(wn * 16 + (lane & 7)) * 144u) +
                          (uint32_t)((g8 & 1) * 16) +
                          (uint32_t)((g8 >> 1) * (B_LO_OFF - B_HI_OFF));

    // prologue: 2 stages in flight
    #pragma unroll
    for (int s = 0; s < 2; s++) {
        gemm_load_stage(sBase, s, s, im0, in0, tid);
        asm volatile("cp.async.commit_group;\n" ::: "memory");
    }

    #pragma unroll 1
    for (int kt = 0; kt < NKT; kt++) {
        asm volatile("cp.async.wait_group 1;\n" ::: "memory");
        __syncthreads();
        if (kt + 2 < NKT) gemm_load_stage(sBase, (kt + 2) % 3, kt + 2, im0, in0, tid);
        asm volatile("cp.async.commit_group;\n" ::: "memory");

        const uint32_t sA  = sBase + (kt % 3) * STG;
        const uint32_t sBh = sA + B_HI_OFF;

        #pragma unroll
        for (int kk = 0; kk < 4; kk++) {
            uint32_t af[4][4];
            #pragma unroll
            for (int mt = 0; mt < 4; mt++) {
                const uint32_t addr = sA + (wm * 64 + mt * 16 + arow) * 144 + kk * 32 + acol;
                asm volatile("ldmatrix.sync.aligned.m8n8.x4.shared.b16 {%0,%1,%2,%3}, [%4];\n"
                             : "=r"(af[mt][0]), "=r"(af[mt][1]),
                               "=r"(af[mt][2]), "=r"(af[mt][3]) : "r"(addr));
            }
            uint32_t bf[2][4];
            #pragma unroll
            for (int nt = 0; nt < 2; nt++) {
                const uint32_t addr = sBh + bOff + nt * 8 * 144 + kk * 32;
                asm volatile("ldmatrix.sync.aligned.m8n8.x4.shared.b16 {%0,%1,%2,%3}, [%4];\n"
                             : "=r"(bf[nt][0]), "=r"(bf[nt][1]),
                               "=r"(bf[nt][2]), "=r"(bf[nt][3]) : "r"(addr));
            }
            #pragma unroll
            for (int mt = 0; mt < 4; mt++)
                #pragma unroll
                for (int nt = 0; nt < 2; nt++) {
                    IMMA_S8(accHi[mt][nt], af[mt], bf[nt][0], bf[nt][1]);
                    IMMA_U8(accLo[mt][nt], af[mt], bf[nt][2], bf[nt][3]);
                }
        }
    }

    // ---- epilogue: score2 = (1/2048) * sum_d (256*Ghi + Glo) * a2[d][i] ----
    __syncthreads();
    float* sRed = (float*)sm;            // [128][4]
    const int qid = lane >> 2, mem = lane & 3;
    #pragma unroll
    for (int mt = 0; mt < 4; mt++) {
        #pragma unroll
        for (int sub = 0; sub < 2; sub++) {
            const int i = im0 + wm * 64 + mt * 16 + qid + 8 * sub;
            float part = 0.f;
            #pragma unroll
            for (int nt = 0; nt < 2; nt++) {
                #pragma unroll
                for (int cp = 0; cp < 2; cp++) {
                    const int full = (accHi[mt][nt][sub * 2 + cp] << 8) + accLo[mt][nt][sub * 2 + cp];
                    const int dd = wn * 16 + nt * 8 + 2 * mem + cp;
                    part = fmaf((float)full, __ldg(&a[(64 + dd) * NN + i]), part);
                }
            }
            part += __shfl_xor_sync(0xffffffffu, part, 1);
            part += __shfl_xor_sync(0xffffffffu, part, 2);
            if (mem == 0) sRed[(wm * 64 + mt * 16 + qid + 8 * sub) * 4 + wn] = part;
        }
    }
    __syncthreads();
    if (tid < 128) {
        const int i = im0 + tid;
        const float s2 = (sRed[tid * 4 + 0] + sRed[tid * 4 + 1] +
                          sRed[tid * 4 + 2] + sRed[tid * 4 + 3]) * (1.f / 2048.f);
        g_score[blockIdx.y * NN + i] = s2 + g_score1[blockIdx.y * NN + i];
    }
}

// ============================================================================
// k_out: h_prime = leaky( score[b][i] * hsum[b][d] )
// ============================================================================
__global__ void __launch_bounds__(256) k_out(float* __restrict__ out)
{
    const int idx = blockIdx.x * 256 + threadIdx.x;
    const int d4 = idx & 15;
    const int i  = (idx >> 4) & 4095;
    const int b  = idx >> 16;
    const float sc = (i == 0) ? 0.f : g_score[b * NN + i];
    const float4 hs = reinterpret_cast<const float4*>(g_hsum)[b * 16 + d4];
    float4 v; float t;
    t = sc * hs.x; v.x = (t >= 0.f) ? t : 0.2f * t;
    t = sc * hs.y; v.y = (t >= 0.f) ? t : 0.2f * t;
    t = sc * hs.z; v.z = (t >= 0.f) ? t : 0.2f * t;
    t = sc * hs.w; v.w = (t >= 0.f) ? t : 0.2f * t;
    reinterpret_cast<float4*>(out)[idx] = v;
}

// ============================================================================
extern "C" void kernel_launch(void* const* d_in, const int* in_sizes, int n_in,
                              void* d_out, int out_size)
{
    const float* inp = nullptr; const float* W = nullptr;
    const float* a = nullptr;   const int* adj = nullptr;
    for (int i = 0; i < n_in; i++) {
        switch (in_sizes[i]) {
            case 8388608:  inp = (const float*)d_in[i]; break;
            case 4096:     W   = (const float*)d_in[i]; break;
            case 524288:   a   = (const float*)d_in[i]; break;
            case 16777216: adj = (const int*)d_in[i];   break;
            default: break;
        }
    }
    if (!inp) inp = (const float*)d_in[0];
    if (!W)   W   = (const float*)d_in[1];
    if (!a)   a   = (const float*)d_in[2];
    if (!adj) adj = (const int*)d_in[3];

    cudaFuncSetAttribute(k_prep, cudaFuncAttributeMaxDynamicSharedMemorySize, 102656);
    cudaFuncSetAttribute(k_gemm, cudaFuncAttributeMaxDynamicSharedMemorySize, 3 * STG);

    k_prep<<<dim3(32, 32), 256, 102656>>>(inp, W, a);
    k_mask<<<dim3(32, 64), 256>>>(adj);
    k_hsum_final<<<8, 256>>>();
    k_gemm<<<dim3(32, 32), 256, 3 * STG>>>(a);
    k_out<<<8192, 256>>>((float*)d_out);
}